// round 2
// baseline (speedup 1.0000x reference)
#include <cuda_runtime.h>

#define EMBED 1024
#define NHEAD 16
#define HDIM  64
#define BATCH 4
#define SEQ   2048
#define MTOT  (BATCH*SEQ)      /* 8192 */
#define QKVF  (3*EMBED)        /* 3072 */

// Scratch (device globals: allocation-free per harness rules)
__device__ float g_qkv[(size_t)MTOT * QKVF];   // [M, 3C]
__device__ float g_att[(size_t)MTOT * EMBED];  // [M, C]

// ---------------------------------------------------------------------------
// SGEMM: C[M,N] = A[M,K] @ B[N,K]^T + bias[N]   (both A and B are K-major)
// 128x128 block tile, BK=8, 256 threads, 8x8 microtile per thread.
// ---------------------------------------------------------------------------
__global__ __launch_bounds__(256) void sgemm_bias(
    const float* __restrict__ A, const float* __restrict__ Bm,
    const float* __restrict__ bias, float* __restrict__ C,
    int M, int N, int K)
{
  __shared__ float As[8][128];
  __shared__ float Bs[8][128];

  const int tid = threadIdx.x;
  const int tx  = tid & 15;        // 0..15 -> N microtiles
  const int ty  = tid >> 4;        // 0..15 -> M microtiles
  const int m0  = blockIdx.y * 128;
  const int n0  = blockIdx.x * 128;

  // global load mapping: each thread loads one float4 of A tile, one of B tile
  const int lr = tid >> 1;               // row within tile 0..127
  const int lc = (tid & 1) << 2;         // col 0 or 4
  const float* Ag = A  + (size_t)(m0 + lr) * K + lc;
  const float* Bg = Bm + (size_t)(n0 + lr) * K + lc;

  float acc[8][8];
  #pragma unroll
  for (int i = 0; i < 8; i++)
    #pragma unroll
    for (int j = 0; j < 8; j++) acc[i][j] = 0.0f;

  for (int k0 = 0; k0 < K; k0 += 8) {
    float4 av = *(const float4*)(Ag + k0);
    float4 bv = *(const float4*)(Bg + k0);
    __syncthreads();
    As[lc+0][lr] = av.x; As[lc+1][lr] = av.y; As[lc+2][lr] = av.z; As[lc+3][lr] = av.w;
    Bs[lc+0][lr] = bv.x; Bs[lc+1][lr] = bv.y; Bs[lc+2][lr] = bv.z; Bs[lc+3][lr] = bv.w;
    __syncthreads();

    #pragma unroll
    for (int k = 0; k < 8; k++) {
      float4 a0 = *(const float4*)&As[k][ty*8];
      float4 a1 = *(const float4*)&As[k][ty*8+4];
      float4 b0 = *(const float4*)&Bs[k][tx*8];
      float4 b1 = *(const float4*)&Bs[k][tx*8+4];
      float ar[8] = {a0.x,a0.y,a0.z,a0.w,a1.x,a1.y,a1.z,a1.w};
      float br[8] = {b0.x,b0.y,b0.z,b0.w,b1.x,b1.y,b1.z,b1.w};
      #pragma unroll
      for (int i = 0; i < 8; i++)
        #pragma unroll
        for (int j = 0; j < 8; j++)
          acc[i][j] += ar[i] * br[j];
    }
  }

  #pragma unroll
  for (int i = 0; i < 8; i++) {
    int m = m0 + ty*8 + i;
    #pragma unroll
    for (int j = 0; j < 8; j += 4) {
      int n = n0 + tx*8 + j;
      float4 v;
      v.x = acc[i][j+0] + bias[n+0];
      v.y = acc[i][j+1] + bias[n+1];
      v.z = acc[i][j+2] + bias[n+2];
      v.w = acc[i][j+3] + bias[n+3];
      *(float4*)(C + (size_t)m * N + n) = v;
    }
  }
}

// ---------------------------------------------------------------------------
// Flash attention (causal, fp32 online softmax).
// Grid: (SEQ/64, B*H).  128 threads: tx = tid&7 (8 col groups), ty = tid>>3
// (16 row groups). Each thread owns 4 q-rows x 8 columns (cols strided:
// c = tx + 8*j so hot smem loads are conflict-free).
// Smem: Qt[d][r] stride 65, Kt[d][c] stride 65, Vs[k][d] stride 64,
//       Ps[r][k] stride 65.
// ---------------------------------------------------------------------------
#define FS_QT 0
#define FS_KT (64*65)
#define FS_VS (2*64*65)
#define FS_PS (2*64*65 + 64*64)
#define FS_TOTAL (2*64*65 + 64*64 + 64*65)   /* 16576 floats = 66304 B */

__global__ __launch_bounds__(128) void flash_kernel(
    const float* __restrict__ qkv, float* __restrict__ out)
{
  extern __shared__ float sm[];
  float* Qt = sm + FS_QT;
  float* Kt = sm + FS_KT;
  float* Vs = sm + FS_VS;
  float* Ps = sm + FS_PS;

  const int tid = threadIdx.x;
  const int tx = tid & 7;
  const int ty = tid >> 3;
  const int qb = blockIdx.x;
  const int bh = blockIdx.y;
  const int b  = bh >> 4;
  const int h  = bh & 15;
  const int q0 = qb * 64;

  const float* qbase = qkv + ((size_t)b * SEQ + q0) * QKVF + h * HDIM;
  const float* kbase = qkv + ((size_t)b * SEQ) * QKVF + EMBED + h * HDIM;
  const float* vbase = kbase + EMBED;

  // Load Q tile (scaled by 1/sqrt(D) = 0.125), store d-major.
  #pragma unroll
  for (int e = tid; e < 64*64; e += 128) {
    int r = e >> 6, d = e & 63;
    Qt[d*65 + r] = qbase[(size_t)r * QKVF + d] * 0.125f;
  }

  float m_i[4], l_i[4], o[4][8];
  #pragma unroll
  for (int i = 0; i < 4; i++) {
    m_i[i] = -1e30f; l_i[i] = 0.0f;
    #pragma unroll
    for (int j = 0; j < 8; j++) o[i][j] = 0.0f;
  }

  for (int kv = 0; kv <= qb; kv++) {
    const int k0 = kv * 64;
    __syncthreads();   // previous iteration's Ps/Vs reads must be done
    #pragma unroll
    for (int e = tid; e < 64*64; e += 128) {
      int r = e >> 6, d = e & 63;
      float kval = kbase[(size_t)(k0 + r) * QKVF + d];
      float vval = vbase[(size_t)(k0 + r) * QKVF + d];
      Kt[d*65 + r] = kval;
      Vs[r*64 + d] = vval;
    }
    __syncthreads();

    // S = Q @ K^T  (outer product over d)
    float s[4][8];
    #pragma unroll
    for (int i = 0; i < 4; i++)
      #pragma unroll
      for (int j = 0; j < 8; j++) s[i][j] = 0.0f;

    #pragma unroll 4
    for (int d = 0; d < 64; d++) {
      float qf[4], kf[8];
      #pragma unroll
      for (int i = 0; i < 4; i++) qf[i] = Qt[d*65 + ty*4 + i];
      #pragma unroll
      for (int j = 0; j < 8; j++) kf[j] = Kt[d*65 + tx + 8*j];
      #pragma unroll
      for (int i = 0; i < 4; i++)
        #pragma unroll
        for (int j = 0; j < 8; j++)
          s[i][j] += qf[i] * kf[j];
    }

    // Causal mask + online softmax update
    const bool diag = (kv == qb);
    #pragma unroll
    for (int i = 0; i < 4; i++) {
      int qg = q0 + ty*4 + i;
      float mx = -1e30f;
      #pragma unroll
      for (int j = 0; j < 8; j++) {
        if (diag && (k0 + tx + 8*j) > qg) s[i][j] = -1e30f;
        mx = fmaxf(mx, s[i][j]);
      }
      mx = fmaxf(mx, __shfl_xor_sync(0xffffffffu, mx, 1));
      mx = fmaxf(mx, __shfl_xor_sync(0xffffffffu, mx, 2));
      mx = fmaxf(mx, __shfl_xor_sync(0xffffffffu, mx, 4));
      float mnew  = fmaxf(m_i[i], mx);
      float alpha = __expf(m_i[i] - mnew);
      m_i[i] = mnew;
      float rs = 0.0f;
      #pragma unroll
      for (int j = 0; j < 8; j++) {
        s[i][j] = __expf(s[i][j] - mnew);
        rs += s[i][j];
      }
      rs += __shfl_xor_sync(0xffffffffu, rs, 1);
      rs += __shfl_xor_sync(0xffffffffu, rs, 2);
      rs += __shfl_xor_sync(0xffffffffu, rs, 4);
      l_i[i] = l_i[i] * alpha + rs;
      #pragma unroll
      for (int j = 0; j < 8; j++) o[i][j] *= alpha;
    }

    // P to smem
    #pragma unroll
    for (int i = 0; i < 4; i++)
      #pragma unroll
      for (int j = 0; j < 8; j++)
        Ps[(ty*4 + i)*65 + tx + 8*j] = s[i][j];
    __syncthreads();

    // O += P @ V
    #pragma unroll 4
    for (int k = 0; k < 64; k++) {
      float pf[4], vf[8];
      #pragma unroll
      for (int i = 0; i < 4; i++) pf[i] = Ps[(ty*4 + i)*65 + k];
      #pragma unroll
      for (int j = 0; j < 8; j++) vf[j] = Vs[k*64 + tx + 8*j];
      #pragma unroll
      for (int i = 0; i < 4; i++)
        #pragma unroll
        for (int j = 0; j < 8; j++)
          o[i][j] += pf[i] * vf[j];
    }
  }

  // Epilogue: normalize and write to [B,T,C] layout (c = h*64 + d)
  #pragma unroll
  for (int i = 0; i < 4; i++) {
    float inv = 1.0f / l_i[i];
    int r = q0 + ty*4 + i;
    float* orow = out + ((size_t)b * SEQ + r) * EMBED + h * HDIM;
    #pragma unroll
    for (int j = 0; j < 8; j++)
      orow[tx + 8*j] = o[i][j] * inv;
  }
}

// ---------------------------------------------------------------------------
extern "C" void kernel_launch(void* const* d_in, const int* in_sizes, int n_in,
                              void* d_out, int out_size)
{
  (void)in_sizes; (void)n_in; (void)out_size;
  const float* x     = (const float*)d_in[0];
  const float* qkv_w = (const float*)d_in[1];
  const float* qkv_b = (const float*)d_in[2];
  const float* out_w = (const float*)d_in[3];
  const float* out_b = (const float*)d_in[4];
  float* y = (float*)d_out;

  float *qkv = nullptr, *att = nullptr;
  cudaGetSymbolAddress((void**)&qkv, g_qkv);
  cudaGetSymbolAddress((void**)&att, g_att);

  cudaFuncSetAttribute(flash_kernel,
                       cudaFuncAttributeMaxDynamicSharedMemorySize,
                       FS_TOTAL * (int)sizeof(float));

  // 1) QKV projection: [8192,1024] @ [3072,1024]^T + b
  sgemm_bias<<<dim3(QKVF/128, MTOT/128), 256>>>(x, qkv_w, qkv_b, qkv,
                                                MTOT, QKVF, EMBED);
  // 2) Causal flash attention
  flash_kernel<<<dim3(SEQ/64, BATCH*NHEAD), 128, FS_TOTAL*(int)sizeof(float)>>>(qkv, att);
  // 3) Output projection: [8192,1024] @ [1024,1024]^T + b
  sgemm_bias<<<dim3(EMBED/128, MTOT/128), 256>>>(att, out_w, out_b, y,
                                                 MTOT, EMBED, EMBED);
}

// round 3
// speedup vs baseline: 1.0046x; 1.0046x over previous
#include <cuda_runtime.h>

#define EMBED 1024
#define NHEAD 16
#define HDIM  64
#define BATCH 4
#define SEQ   2048
#define MTOT  (BATCH*SEQ)      /* 8192 */
#define QKVF  (3*EMBED)        /* 3072 */

// Scratch (device globals: allocation-free per harness rules)
__device__ float g_qkv[(size_t)MTOT * QKVF];   // [M, 3C]
__device__ float g_att[(size_t)MTOT * EMBED];  // [M, C]

// ---------------------------------------------------------------------------
// SGEMM: C[M,N] = A[M,K] @ B[N,K]^T + bias[N]   (both A and B are K-major)
// 128x128 block tile, BK=8, 256 threads, 8x8 microtile per thread.
// ---------------------------------------------------------------------------
__global__ __launch_bounds__(256) void sgemm_bias(
    const float* __restrict__ A, const float* __restrict__ Bm,
    const float* __restrict__ bias, float* __restrict__ C,
    int M, int N, int K)
{
  __shared__ float As[8][128];
  __shared__ float Bs[8][128];

  const int tid = threadIdx.x;
  const int tx  = tid & 15;        // 0..15 -> N microtiles
  const int ty  = tid >> 4;        // 0..15 -> M microtiles
  const int m0  = blockIdx.y * 128;
  const int n0  = blockIdx.x * 128;

  // global load mapping: each thread loads one float4 of A tile, one of B tile
  const int lr = tid >> 1;               // row within tile 0..127
  const int lc = (tid & 1) << 2;         // col 0 or 4
  const float* Ag = A  + (size_t)(m0 + lr) * K + lc;
  const float* Bg = Bm + (size_t)(n0 + lr) * K + lc;

  float acc[8][8];
  #pragma unroll
  for (int i = 0; i < 8; i++)
    #pragma unroll
    for (int j = 0; j < 8; j++) acc[i][j] = 0.0f;

  for (int k0 = 0; k0 < K; k0 += 8) {
    float4 av = *(const float4*)(Ag + k0);
    float4 bv = *(const float4*)(Bg + k0);
    __syncthreads();
    As[lc+0][lr] = av.x; As[lc+1][lr] = av.y; As[lc+2][lr] = av.z; As[lc+3][lr] = av.w;
    Bs[lc+0][lr] = bv.x; Bs[lc+1][lr] = bv.y; Bs[lc+2][lr] = bv.z; Bs[lc+3][lr] = bv.w;
    __syncthreads();

    #pragma unroll
    for (int k = 0; k < 8; k++) {
      float4 a0 = *(const float4*)&As[k][ty*8];
      float4 a1 = *(const float4*)&As[k][ty*8+4];
      float4 b0 = *(const float4*)&Bs[k][tx*8];
      float4 b1 = *(const float4*)&Bs[k][tx*8+4];
      float ar[8] = {a0.x,a0.y,a0.z,a0.w,a1.x,a1.y,a1.z,a1.w};
      float br[8] = {b0.x,b0.y,b0.z,b0.w,b1.x,b1.y,b1.z,b1.w};
      #pragma unroll
      for (int i = 0; i < 8; i++)
        #pragma unroll
        for (int j = 0; j < 8; j++)
          acc[i][j] += ar[i] * br[j];
    }
  }

  #pragma unroll
  for (int i = 0; i < 8; i++) {
    int m = m0 + ty*8 + i;
    #pragma unroll
    for (int j = 0; j < 8; j += 4) {
      int n = n0 + tx*8 + j;
      float4 v;
      v.x = acc[i][j+0] + bias[n+0];
      v.y = acc[i][j+1] + bias[n+1];
      v.z = acc[i][j+2] + bias[n+2];
      v.w = acc[i][j+3] + bias[n+3];
      *(float4*)(C + (size_t)m * N + n) = v;
    }
  }
}

// ---------------------------------------------------------------------------
// Flash attention (causal, fp32 online softmax).
// Grid: (SEQ/64, B*H).  128 threads: tx = tid&7 (8 col groups), ty = tid>>3
// (16 row groups). Each thread owns 4 q-rows x 8 columns (cols strided:
// c = tx + 8*j so hot smem loads are conflict-free).
// Smem: Qt[d][r] stride 65, Kt[d][c] stride 65, Vs[k][d] stride 64,
//       Ps[r][k] stride 65.
// ---------------------------------------------------------------------------
#define FS_QT 0
#define FS_KT (64*65)
#define FS_VS (2*64*65)
#define FS_PS (2*64*65 + 64*64)
#define FS_TOTAL (2*64*65 + 64*64 + 64*65)   /* 16576 floats = 66304 B */

__global__ __launch_bounds__(128) void flash_kernel(
    const float* __restrict__ qkv, float* __restrict__ out)
{
  extern __shared__ float sm[];
  float* Qt = sm + FS_QT;
  float* Kt = sm + FS_KT;
  float* Vs = sm + FS_VS;
  float* Ps = sm + FS_PS;

  const int tid = threadIdx.x;
  const int tx = tid & 7;
  const int ty = tid >> 3;
  const int qb = blockIdx.x;
  const int bh = blockIdx.y;
  const int b  = bh >> 4;
  const int h  = bh & 15;
  const int q0 = qb * 64;

  const float* qbase = qkv + ((size_t)b * SEQ + q0) * QKVF + h * HDIM;
  const float* kbase = qkv + ((size_t)b * SEQ) * QKVF + EMBED + h * HDIM;
  const float* vbase = kbase + EMBED;

  // Load Q tile (scaled by 1/sqrt(D) = 0.125), store d-major.
  #pragma unroll
  for (int e = tid; e < 64*64; e += 128) {
    int r = e >> 6, d = e & 63;
    Qt[d*65 + r] = qbase[(size_t)r * QKVF + d] * 0.125f;
  }

  float m_i[4], l_i[4], o[4][8];
  #pragma unroll
  for (int i = 0; i < 4; i++) {
    m_i[i] = -1e30f; l_i[i] = 0.0f;
    #pragma unroll
    for (int j = 0; j < 8; j++) o[i][j] = 0.0f;
  }

  for (int kv = 0; kv <= qb; kv++) {
    const int k0 = kv * 64;
    __syncthreads();   // previous iteration's Ps/Vs reads must be done
    #pragma unroll
    for (int e = tid; e < 64*64; e += 128) {
      int r = e >> 6, d = e & 63;
      float kval = kbase[(size_t)(k0 + r) * QKVF + d];
      float vval = vbase[(size_t)(k0 + r) * QKVF + d];
      Kt[d*65 + r] = kval;
      Vs[r*64 + d] = vval;
    }
    __syncthreads();

    // S = Q @ K^T  (outer product over d)
    float s[4][8];
    #pragma unroll
    for (int i = 0; i < 4; i++)
      #pragma unroll
      for (int j = 0; j < 8; j++) s[i][j] = 0.0f;

    #pragma unroll 4
    for (int d = 0; d < 64; d++) {
      float qf[4], kf[8];
      #pragma unroll
      for (int i = 0; i < 4; i++) qf[i] = Qt[d*65 + ty*4 + i];
      #pragma unroll
      for (int j = 0; j < 8; j++) kf[j] = Kt[d*65 + tx + 8*j];
      #pragma unroll
      for (int i = 0; i < 4; i++)
        #pragma unroll
        for (int j = 0; j < 8; j++)
          s[i][j] += qf[i] * kf[j];
    }

    // Causal mask + online softmax update
    const bool diag = (kv == qb);
    #pragma unroll
    for (int i = 0; i < 4; i++) {
      int qg = q0 + ty*4 + i;
      float mx = -1e30f;
      #pragma unroll
      for (int j = 0; j < 8; j++) {
        if (diag && (k0 + tx + 8*j) > qg) s[i][j] = -1e30f;
        mx = fmaxf(mx, s[i][j]);
      }
      mx = fmaxf(mx, __shfl_xor_sync(0xffffffffu, mx, 1));
      mx = fmaxf(mx, __shfl_xor_sync(0xffffffffu, mx, 2));
      mx = fmaxf(mx, __shfl_xor_sync(0xffffffffu, mx, 4));
      float mnew  = fmaxf(m_i[i], mx);
      float alpha = __expf(m_i[i] - mnew);
      m_i[i] = mnew;
      float rs = 0.0f;
      #pragma unroll
      for (int j = 0; j < 8; j++) {
        s[i][j] = __expf(s[i][j] - mnew);
        rs += s[i][j];
      }
      rs += __shfl_xor_sync(0xffffffffu, rs, 1);
      rs += __shfl_xor_sync(0xffffffffu, rs, 2);
      rs += __shfl_xor_sync(0xffffffffu, rs, 4);
      l_i[i] = l_i[i] * alpha + rs;
      #pragma unroll
      for (int j = 0; j < 8; j++) o[i][j] *= alpha;
    }

    // P to smem
    #pragma unroll
    for (int i = 0; i < 4; i++)
      #pragma unroll
      for (int j = 0; j < 8; j++)
        Ps[(ty*4 + i)*65 + tx + 8*j] = s[i][j];
    __syncthreads();

    // O += P @ V
    #pragma unroll 4
    for (int k = 0; k < 64; k++) {
      float pf[4], vf[8];
      #pragma unroll
      for (int i = 0; i < 4; i++) pf[i] = Ps[(ty*4 + i)*65 + k];
      #pragma unroll
      for (int j = 0; j < 8; j++) vf[j] = Vs[k*64 + tx + 8*j];
      #pragma unroll
      for (int i = 0; i < 4; i++)
        #pragma unroll
        for (int j = 0; j < 8; j++)
          o[i][j] += pf[i] * vf[j];
    }
  }

  // Epilogue: normalize and write to [B,T,C] layout (c = h*64 + d)
  #pragma unroll
  for (int i = 0; i < 4; i++) {
    float inv = 1.0f / l_i[i];
    int r = q0 + ty*4 + i;
    float* orow = out + ((size_t)b * SEQ + r) * EMBED + h * HDIM;
    #pragma unroll
    for (int j = 0; j < 8; j++)
      orow[tx + 8*j] = o[i][j] * inv;
  }
}

// ---------------------------------------------------------------------------
extern "C" void kernel_launch(void* const* d_in, const int* in_sizes, int n_in,
                              void* d_out, int out_size)
{
  (void)in_sizes; (void)n_in; (void)out_size;
  const float* x     = (const float*)d_in[0];
  const float* qkv_w = (const float*)d_in[1];
  const float* qkv_b = (const float*)d_in[2];
  const float* out_w = (const float*)d_in[3];
  const float* out_b = (const float*)d_in[4];
  float* y = (float*)d_out;

  float *qkv = nullptr, *att = nullptr;
  cudaGetSymbolAddress((void**)&qkv, g_qkv);
  cudaGetSymbolAddress((void**)&att, g_att);

  cudaFuncSetAttribute(flash_kernel,
                       cudaFuncAttributeMaxDynamicSharedMemorySize,
                       FS_TOTAL * (int)sizeof(float));

  // 1) QKV projection: [8192,1024] @ [3072,1024]^T + b
  sgemm_bias<<<dim3(QKVF/128, MTOT/128), 256>>>(x, qkv_w, qkv_b, qkv,
                                                MTOT, QKVF, EMBED);
  // 2) Causal flash attention
  flash_kernel<<<dim3(SEQ/64, BATCH*NHEAD), 128, FS_TOTAL*(int)sizeof(float)>>>(qkv, att);
  // 3) Output projection: [8192,1024] @ [1024,1024]^T + b
  sgemm_bias<<<dim3(EMBED/128, MTOT/128), 256>>>(att, out_w, out_b, y,
                                                 MTOT, EMBED, EMBED);
}

// round 4
// speedup vs baseline: 1.4811x; 1.4742x over previous
#include <cuda_runtime.h>
#include <cstdint>

#define EMBED 1024
#define NHEAD 16
#define HDIM  64
#define BATCH 4
#define SEQ   2048
#define MTOT  (BATCH*SEQ)      /* 8192 */
#define QKVF  (3*EMBED)        /* 3072 */

// Scratch (device globals: allocation-free per harness rules)
__device__ float g_qkv[(size_t)MTOT * QKVF];   // [M, 3C]
__device__ float g_att[(size_t)MTOT * EMBED];  // [M, C]

// ---------------------------------------------------------------------------
// TF32 tensor-core GEMM: C[M,N] = A[M,K] @ B[N,K]^T + bias[N]
// (A and B both K-major). Block tile 128x128x32, 256 threads = 8 warps (4x2),
// warp tile 32x64 via mma.sync.m16n8k8.row.col.f32.tf32.tf32.f32.
// Smem holds operands already converted to tf32 AND permuted into exact
// mma fragment order, so the read side is conflict-free LDS.128 / LDS.64.
// ---------------------------------------------------------------------------

__device__ __forceinline__ uint32_t f2tf32(float f) {
  uint32_t u;
  asm("cvt.rna.tf32.f32 %0, %1;" : "=r"(u) : "f"(f));
  return u;
}

__device__ __forceinline__ void mma_tf32(float c[4], const uint4& a, const uint2& b) {
  asm volatile(
    "mma.sync.aligned.m16n8k8.row.col.f32.tf32.tf32.f32 "
    "{%0,%1,%2,%3}, {%4,%5,%6,%7}, {%8,%9}, {%0,%1,%2,%3};\n"
    : "+f"(c[0]), "+f"(c[1]), "+f"(c[2]), "+f"(c[3])
    : "r"(a.x), "r"(a.y), "r"(a.z), "r"(a.w), "r"(b.x), "r"(b.y));
}

__global__ __launch_bounds__(256) void gemm_tf32(
    const float* __restrict__ A, const float* __restrict__ Bm,
    const float* __restrict__ bias, float* __restrict__ C,
    int M, int N, int K)
{
  // Fragment-layout smem: A: [mt(8)][kt(4)][lane(32)][reg(4)]  (tf32 bits)
  //                       B: [nt(16)][kt(4)][lane(32)][reg(2)]
  __shared__ __align__(16) uint32_t AsF[8 * 4 * 32 * 4];   // 4096
  __shared__ __align__(16) uint32_t BsF[16 * 4 * 32 * 2];  // 4096

  const int tid  = threadIdx.x;
  const int lane = tid & 31;
  const int wid  = tid >> 5;
  const int wm   = wid & 3;    // 0..3 -> 32-row strip
  const int wn   = wid >> 2;   // 0..1 -> 64-col strip
  const int m0   = blockIdx.y * 128;
  const int n0   = blockIdx.x * 128;

  float acc[2][8][4];
  #pragma unroll
  for (int i = 0; i < 2; i++)
    #pragma unroll
    for (int j = 0; j < 8; j++)
      #pragma unroll
      for (int r = 0; r < 4; r++) acc[i][j][r] = 0.0f;

  float4 va[4], vb[4];

  // ---- global tile load (registers): 4 float4 of A + 4 of B per thread ----
  auto load_tiles = [&](int k0) {
    #pragma unroll
    for (int i = 0; i < 4; i++) {
      int idx = tid + 256 * i;          // 0..1023
      int row = idx >> 3;               // 0..127
      int c4  = (idx & 7) << 2;         // 0,4,..,28
      va[i] = *(const float4*)(A  + (size_t)(m0 + row) * K + k0 + c4);
      vb[i] = *(const float4*)(Bm + (size_t)(n0 + row) * K + k0 + c4);
    }
  };

  // ---- convert to tf32 + scatter into fragment layout ----
  auto store_tiles = [&]() {
    #pragma unroll
    for (int i = 0; i < 4; i++) {
      int idx = tid + 256 * i;
      int row = idx >> 3;
      int c4  = (idx & 7) << 2;
      float af[4] = {va[i].x, va[i].y, va[i].z, va[i].w};
      float bf[4] = {vb[i].x, vb[i].y, vb[i].z, vb[i].w};
      #pragma unroll
      for (int j = 0; j < 4; j++) {
        int k  = c4 + j;
        int kt = k >> 3, kk = k & 7;
        // A: mt = row>>4, r = row&15
        {
          int mt = row >> 4, r = row & 15;
          int ln  = ((r & 7) << 2) | (kk & 3);
          int reg = (r >> 3) | ((kk >> 2) << 1);
          AsF[((((mt << 2) | kt) << 5 | ln) << 2) | reg] = f2tf32(af[j]);
        }
        // B: nt = row>>3, c = row&7
        {
          int nt = row >> 3, c = row & 7;
          int ln  = (c << 2) | (kk & 3);
          int reg = kk >> 2;
          BsF[((((nt << 2) | kt) << 5 | ln) << 1) | reg] = f2tf32(bf[j]);
        }
      }
    }
  };

  // ---- pipeline: prefetch next K-chunk in regs while computing current ----
  load_tiles(0);
  store_tiles();
  __syncthreads();

  const int nk = K >> 5;   // K / 32
  for (int it = 0; it < nk; it++) {
    if (it + 1 < nk) load_tiles((it + 1) << 5);

    #pragma unroll
    for (int kt = 0; kt < 4; kt++) {
      uint4 af0 = *(const uint4*)&AsF[((((wm * 2 + 0) << 2) | kt) << 5 | lane) << 2];
      uint4 af1 = *(const uint4*)&AsF[((((wm * 2 + 1) << 2) | kt) << 5 | lane) << 2];
      #pragma unroll
      for (int nt = 0; nt < 8; nt++) {
        uint2 bf = *(const uint2*)&BsF[((((wn * 8 + nt) << 2) | kt) << 5 | lane) << 1];
        mma_tf32(acc[0][nt], af0, bf);
        mma_tf32(acc[1][nt], af1, bf);
      }
    }

    if (it + 1 < nk) {
      __syncthreads();
      store_tiles();
      __syncthreads();
    }
  }

  // ---- epilogue: c0:(g,2t) c1:(g,2t+1) c2:(g+8,2t) c3:(g+8,2t+1) ----
  const int gm_base = m0 + wm * 32 + (lane >> 2);
  const int gn_base = n0 + wn * 64 + ((lane & 3) << 1);
  #pragma unroll
  for (int mt2 = 0; mt2 < 2; mt2++) {
    #pragma unroll
    for (int nt = 0; nt < 8; nt++) {
      int gm = gm_base + mt2 * 16;
      int gn = gn_base + nt * 8;
      float b0 = bias[gn], b1 = bias[gn + 1];
      float2 v0 = make_float2(acc[mt2][nt][0] + b0, acc[mt2][nt][1] + b1);
      float2 v1 = make_float2(acc[mt2][nt][2] + b0, acc[mt2][nt][3] + b1);
      *(float2*)(C + (size_t)gm * N + gn)       = v0;
      *(float2*)(C + (size_t)(gm + 8) * N + gn) = v1;
    }
  }
}

// ---------------------------------------------------------------------------
// Flash attention (causal, fp32 online softmax) — unchanged from R2.
// ---------------------------------------------------------------------------
#define FS_QT 0
#define FS_KT (64*65)
#define FS_VS (2*64*65)
#define FS_PS (2*64*65 + 64*64)
#define FS_TOTAL (2*64*65 + 64*64 + 64*65)   /* 16576 floats = 66304 B */

__global__ __launch_bounds__(128) void flash_kernel(
    const float* __restrict__ qkv, float* __restrict__ out)
{
  extern __shared__ float sm[];
  float* Qt = sm + FS_QT;
  float* Kt = sm + FS_KT;
  float* Vs = sm + FS_VS;
  float* Ps = sm + FS_PS;

  const int tid = threadIdx.x;
  const int tx = tid & 7;
  const int ty = tid >> 3;
  const int qb = blockIdx.x;
  const int bh = blockIdx.y;
  const int b  = bh >> 4;
  const int h  = bh & 15;
  const int q0 = qb * 64;

  const float* qbase = qkv + ((size_t)b * SEQ + q0) * QKVF + h * HDIM;
  const float* kbase = qkv + ((size_t)b * SEQ) * QKVF + EMBED + h * HDIM;
  const float* vbase = kbase + EMBED;

  #pragma unroll
  for (int e = tid; e < 64*64; e += 128) {
    int r = e >> 6, d = e & 63;
    Qt[d*65 + r] = qbase[(size_t)r * QKVF + d] * 0.125f;
  }

  float m_i[4], l_i[4], o[4][8];
  #pragma unroll
  for (int i = 0; i < 4; i++) {
    m_i[i] = -1e30f; l_i[i] = 0.0f;
    #pragma unroll
    for (int j = 0; j < 8; j++) o[i][j] = 0.0f;
  }

  for (int kv = 0; kv <= qb; kv++) {
    const int k0 = kv * 64;
    __syncthreads();
    #pragma unroll
    for (int e = tid; e < 64*64; e += 128) {
      int r = e >> 6, d = e & 63;
      float kval = kbase[(size_t)(k0 + r) * QKVF + d];
      float vval = vbase[(size_t)(k0 + r) * QKVF + d];
      Kt[d*65 + r] = kval;
      Vs[r*64 + d] = vval;
    }
    __syncthreads();

    float s[4][8];
    #pragma unroll
    for (int i = 0; i < 4; i++)
      #pragma unroll
      for (int j = 0; j < 8; j++) s[i][j] = 0.0f;

    #pragma unroll 4
    for (int d = 0; d < 64; d++) {
      float qf[4], kf[8];
      #pragma unroll
      for (int i = 0; i < 4; i++) qf[i] = Qt[d*65 + ty*4 + i];
      #pragma unroll
      for (int j = 0; j < 8; j++) kf[j] = Kt[d*65 + tx + 8*j];
      #pragma unroll
      for (int i = 0; i < 4; i++)
        #pragma unroll
        for (int j = 0; j < 8; j++)
          s[i][j] += qf[i] * kf[j];
    }

    const bool diag = (kv == qb);
    #pragma unroll
    for (int i = 0; i < 4; i++) {
      int qg = q0 + ty*4 + i;
      float mx = -1e30f;
      #pragma unroll
      for (int j = 0; j < 8; j++) {
        if (diag && (k0 + tx + 8*j) > qg) s[i][j] = -1e30f;
        mx = fmaxf(mx, s[i][j]);
      }
      mx = fmaxf(mx, __shfl_xor_sync(0xffffffffu, mx, 1));
      mx = fmaxf(mx, __shfl_xor_sync(0xffffffffu, mx, 2));
      mx = fmaxf(mx, __shfl_xor_sync(0xffffffffu, mx, 4));
      float mnew  = fmaxf(m_i[i], mx);
      float alpha = __expf(m_i[i] - mnew);
      m_i[i] = mnew;
      float rs = 0.0f;
      #pragma unroll
      for (int j = 0; j < 8; j++) {
        s[i][j] = __expf(s[i][j] - mnew);
        rs += s[i][j];
      }
      rs += __shfl_xor_sync(0xffffffffu, rs, 1);
      rs += __shfl_xor_sync(0xffffffffu, rs, 2);
      rs += __shfl_xor_sync(0xffffffffu, rs, 4);
      l_i[i] = l_i[i] * alpha + rs;
      #pragma unroll
      for (int j = 0; j < 8; j++) o[i][j] *= alpha;
    }

    #pragma unroll
    for (int i = 0; i < 4; i++)
      #pragma unroll
      for (int j = 0; j < 8; j++)
        Ps[(ty*4 + i)*65 + tx + 8*j] = s[i][j];
    __syncthreads();

    #pragma unroll 4
    for (int k = 0; k < 64; k++) {
      float pf[4], vf[8];
      #pragma unroll
      for (int i = 0; i < 4; i++) pf[i] = Ps[(ty*4 + i)*65 + k];
      #pragma unroll
      for (int j = 0; j < 8; j++) vf[j] = Vs[k*64 + tx + 8*j];
      #pragma unroll
      for (int i = 0; i < 4; i++)
        #pragma unroll
        for (int j = 0; j < 8; j++)
          o[i][j] += pf[i] * vf[j];
    }
  }

  #pragma unroll
  for (int i = 0; i < 4; i++) {
    float inv = 1.0f / l_i[i];
    int r = q0 + ty*4 + i;
    float* orow = out + ((size_t)b * SEQ + r) * EMBED + h * HDIM;
    #pragma unroll
    for (int j = 0; j < 8; j++)
      orow[tx + 8*j] = o[i][j] * inv;
  }
}

// ---------------------------------------------------------------------------
extern "C" void kernel_launch(void* const* d_in, const int* in_sizes, int n_in,
                              void* d_out, int out_size)
{
  (void)in_sizes; (void)n_in; (void)out_size;
  const float* x     = (const float*)d_in[0];
  const float* qkv_w = (const float*)d_in[1];
  const float* qkv_b = (const float*)d_in[2];
  const float* out_w = (const float*)d_in[3];
  const float* out_b = (const float*)d_in[4];
  float* y = (float*)d_out;

  float *qkv = nullptr, *att = nullptr;
  cudaGetSymbolAddress((void**)&qkv, g_qkv);
  cudaGetSymbolAddress((void**)&att, g_att);

  cudaFuncSetAttribute(flash_kernel,
                       cudaFuncAttributeMaxDynamicSharedMemorySize,
                       FS_TOTAL * (int)sizeof(float));

  // 1) QKV projection: [8192,1024] @ [3072,1024]^T + b  (TF32 tensor cores)
  gemm_tf32<<<dim3(QKVF/128, MTOT/128), 256>>>(x, qkv_w, qkv_b, qkv,
                                               MTOT, QKVF, EMBED);
  // 2) Causal flash attention (fp32)
  flash_kernel<<<dim3(SEQ/64, BATCH*NHEAD), 128, FS_TOTAL*(int)sizeof(float)>>>(qkv, att);
  // 3) Output projection: [8192,1024] @ [1024,1024]^T + b  (TF32 tensor cores)
  gemm_tf32<<<dim3(EMBED/128, MTOT/128), 256>>>(att, out_w, out_b, y,
                                                MTOT, EMBED, EMBED);
}

// round 5
// speedup vs baseline: 2.2976x; 1.5513x over previous
#include <cuda_runtime.h>
#include <cstdint>

#define EMBED 1024
#define NHEAD 16
#define HDIM  64
#define BATCH 4
#define SEQ   2048
#define MTOT  (BATCH*SEQ)      /* 8192 */
#define QKVF  (3*EMBED)        /* 3072 */

// Scratch (device globals: allocation-free per harness rules)
__device__ float g_qkv[(size_t)MTOT * QKVF];   // [M, 3C]
__device__ float g_att[(size_t)MTOT * EMBED];  // [M, C]

__device__ __forceinline__ uint32_t f2tf32(float f) {
  uint32_t u;
  asm("cvt.rna.tf32.f32 %0, %1;" : "=r"(u) : "f"(f));
  return u;
}

__device__ __forceinline__ void mma_tf32(float c[4], const uint4& a, const uint2& b) {
  asm volatile(
    "mma.sync.aligned.m16n8k8.row.col.f32.tf32.tf32.f32 "
    "{%0,%1,%2,%3}, {%4,%5,%6,%7}, {%8,%9}, {%0,%1,%2,%3};\n"
    : "+f"(c[0]), "+f"(c[1]), "+f"(c[2]), "+f"(c[3])
    : "r"(a.x), "r"(a.y), "r"(a.z), "r"(a.w), "r"(b.x), "r"(b.y));
}

// ---------------------------------------------------------------------------
// TF32 tensor-core GEMM (unchanged from R4): C = A @ B^T + bias
// ---------------------------------------------------------------------------
__global__ __launch_bounds__(256) void gemm_tf32(
    const float* __restrict__ A, const float* __restrict__ Bm,
    const float* __restrict__ bias, float* __restrict__ C,
    int M, int N, int K)
{
  __shared__ __align__(16) uint32_t AsF[8 * 4 * 32 * 4];
  __shared__ __align__(16) uint32_t BsF[16 * 4 * 32 * 2];

  const int tid  = threadIdx.x;
  const int lane = tid & 31;
  const int wid  = tid >> 5;
  const int wm   = wid & 3;
  const int wn   = wid >> 2;
  const int m0   = blockIdx.y * 128;
  const int n0   = blockIdx.x * 128;

  float acc[2][8][4];
  #pragma unroll
  for (int i = 0; i < 2; i++)
    #pragma unroll
    for (int j = 0; j < 8; j++)
      #pragma unroll
      for (int r = 0; r < 4; r++) acc[i][j][r] = 0.0f;

  float4 va[4], vb[4];

  auto load_tiles = [&](int k0) {
    #pragma unroll
    for (int i = 0; i < 4; i++) {
      int idx = tid + 256 * i;
      int row = idx >> 3;
      int c4  = (idx & 7) << 2;
      va[i] = *(const float4*)(A  + (size_t)(m0 + row) * K + k0 + c4);
      vb[i] = *(const float4*)(Bm + (size_t)(n0 + row) * K + k0 + c4);
    }
  };

  auto store_tiles = [&]() {
    #pragma unroll
    for (int i = 0; i < 4; i++) {
      int idx = tid + 256 * i;
      int row = idx >> 3;
      int c4  = (idx & 7) << 2;
      float af[4] = {va[i].x, va[i].y, va[i].z, va[i].w};
      float bf[4] = {vb[i].x, vb[i].y, vb[i].z, vb[i].w};
      #pragma unroll
      for (int j = 0; j < 4; j++) {
        int k  = c4 + j;
        int kt = k >> 3, kk = k & 7;
        {
          int mt = row >> 4, r = row & 15;
          int ln  = ((r & 7) << 2) | (kk & 3);
          int reg = (r >> 3) | ((kk >> 2) << 1);
          AsF[((((mt << 2) | kt) << 5 | ln) << 2) | reg] = f2tf32(af[j]);
        }
        {
          int nt = row >> 3, c = row & 7;
          int ln  = (c << 2) | (kk & 3);
          int reg = kk >> 2;
          BsF[((((nt << 2) | kt) << 5 | ln) << 1) | reg] = f2tf32(bf[j]);
        }
      }
    }
  };

  load_tiles(0);
  store_tiles();
  __syncthreads();

  const int nk = K >> 5;
  for (int it = 0; it < nk; it++) {
    if (it + 1 < nk) load_tiles((it + 1) << 5);

    #pragma unroll
    for (int kt = 0; kt < 4; kt++) {
      uint4 af0 = *(const uint4*)&AsF[((((wm * 2 + 0) << 2) | kt) << 5 | lane) << 2];
      uint4 af1 = *(const uint4*)&AsF[((((wm * 2 + 1) << 2) | kt) << 5 | lane) << 2];
      #pragma unroll
      for (int nt = 0; nt < 8; nt++) {
        uint2 bf = *(const uint2*)&BsF[((((wn * 8 + nt) << 2) | kt) << 5 | lane) << 1];
        mma_tf32(acc[0][nt], af0, bf);
        mma_tf32(acc[1][nt], af1, bf);
      }
    }

    if (it + 1 < nk) {
      __syncthreads();
      store_tiles();
      __syncthreads();
    }
  }

  const int gm_base = m0 + wm * 32 + (lane >> 2);
  const int gn_base = n0 + wn * 64 + ((lane & 3) << 1);
  #pragma unroll
  for (int mt2 = 0; mt2 < 2; mt2++) {
    #pragma unroll
    for (int nt = 0; nt < 8; nt++) {
      int gm = gm_base + mt2 * 16;
      int gn = gn_base + nt * 8;
      float b0 = bias[gn], b1 = bias[gn + 1];
      float2 v0 = make_float2(acc[mt2][nt][0] + b0, acc[mt2][nt][1] + b1);
      float2 v1 = make_float2(acc[mt2][nt][2] + b0, acc[mt2][nt][3] + b1);
      *(float2*)(C + (size_t)gm * N + gn)       = v0;
      *(float2*)(C + (size_t)(gm + 8) * N + gn) = v1;
    }
  }
}

// ---------------------------------------------------------------------------
// Flash attention with TF32 tensor cores.
// Block: 128 q-rows x D=64, iterating 64-key tiles. 256 threads = 8 warps,
// each warp owns a 16-row strip (m16n8k8 fragments).
// Smem (uint32 tf32 bits):
//   QF: fragment-layout Q  [w][ks][lane][4]   (scatter once, LDS.128 reads)
//   Kt: [key][d] natural, stride 68 (STS.128 fill, conflict-free b-frag reads)
//   Vs: [key][d] natural, stride 72 (STS.128 fill, conflict-free b-frag reads)
//   Ps: per-warp P tile [w][16][68] (c-frag STS.64, conflict-free a-frag reads)
// ---------------------------------------------------------------------------
#define FQF 0
#define FKT 8192
#define FVS (8192 + 64*68)
#define FPS (8192 + 64*68 + 64*72)
#define FTOT (8192 + 64*68 + 64*72 + 8*16*68)   /* 25856 words = 103424 B */

__global__ __launch_bounds__(256) void flash_tc(
    const float* __restrict__ qkv, float* __restrict__ out)
{
  extern __shared__ uint32_t sm[];
  uint32_t* QF = sm + FQF;
  uint32_t* Kt = sm + FKT;
  uint32_t* Vs = sm + FVS;
  uint32_t* Ps = sm + FPS;

  const int tid  = threadIdx.x;
  const int lane = tid & 31;
  const int w    = tid >> 5;
  const int bx   = blockIdx.x;
  const int bh   = blockIdx.y;
  const int b    = bh >> 4;
  const int h    = bh & 15;
  const int q0   = bx * 128;

  const float* qbase = qkv + ((size_t)b * SEQ + q0) * QKVF + h * HDIM;
  const float* kbase = qkv + ((size_t)b * SEQ) * QKVF + EMBED + h * HDIM;
  const float* vbase = kbase + EMBED;

  // ---- Q scatter into fragment layout (once per block), scaled by 1/8 ----
  for (int e = tid; e < 128 * 16; e += 256) {
    int r = e >> 4, d4 = (e & 15) << 2;
    float4 qv = *(const float4*)(qbase + (size_t)r * QKVF + d4);
    float qf[4] = {qv.x, qv.y, qv.z, qv.w};
    int wq = r >> 4, rr = r & 15;
    #pragma unroll
    for (int j = 0; j < 4; j++) {
      int d = d4 + j, ks = d >> 3, dd = d & 7;
      int ln = ((rr & 7) << 2) | (dd & 3);
      int rg = (rr >> 3) | ((dd >> 2) << 1);
      QF[((((wq << 3) | ks) << 5 | ln) << 2) | rg] = f2tf32(qf[j] * 0.125f);
    }
  }

  const int r0 = lane >> 2;      // 0..7
  const int tq = lane & 3;       // 0..3
  const int qg0 = q0 + w * 16 + r0;
  const int qg1 = qg0 + 8;
  const int qmin = q0 + w * 16;
  const int qmax = qmin + 15;
  const int pw = w * (16 * 68);

  float m0v = -1e30f, m1v = -1e30f, l0v = 0.0f, l1v = 0.0f;
  float o[8][4];
  #pragma unroll
  for (int nt = 0; nt < 8; nt++)
    #pragma unroll
    for (int j = 0; j < 4; j++) o[nt][j] = 0.0f;

  const int nkv = 2 * bx + 2;
  for (int kv = 0; kv < nkv; kv++) {
    const int k0 = kv * 64;
    __syncthreads();   // all warps done reading previous Kt/Vs (and QF ready)
    // ---- fill K/V tiles: vectorized convert + STS.128 ----
    for (int e = tid; e < 64 * 16; e += 256) {
      int r = e >> 4, d4 = (e & 15) << 2;
      float4 kf4 = *(const float4*)(kbase + (size_t)(k0 + r) * QKVF + d4);
      float4 vf4 = *(const float4*)(vbase + (size_t)(k0 + r) * QKVF + d4);
      uint4 ku = make_uint4(f2tf32(kf4.x), f2tf32(kf4.y), f2tf32(kf4.z), f2tf32(kf4.w));
      uint4 vu = make_uint4(f2tf32(vf4.x), f2tf32(vf4.y), f2tf32(vf4.z), f2tf32(vf4.w));
      *(uint4*)&Kt[r * 68 + d4] = ku;
      *(uint4*)&Vs[r * 72 + d4] = vu;
    }
    __syncthreads();

    if (k0 > qmax) continue;   // whole key tile above this warp's rows

    // ---- load Q a-fragments (LDS.128, conflict-free) ----
    uint4 qa[8];
    #pragma unroll
    for (int ks = 0; ks < 8; ks++)
      qa[ks] = *(const uint4*)&QF[(((w << 3) | ks) << 5 | lane) << 2];

    // ---- S = Q @ K^T ----
    float s[8][4];
    #pragma unroll
    for (int nt = 0; nt < 8; nt++) {
      s[nt][0] = s[nt][1] = s[nt][2] = s[nt][3] = 0.0f;
      #pragma unroll
      for (int ks = 0; ks < 8; ks++) {
        uint2 bk;
        bk.x = Kt[(8 * nt + r0) * 68 + 8 * ks + tq];
        bk.y = Kt[(8 * nt + r0) * 68 + 8 * ks + tq + 4];
        mma_tf32(s[nt], qa[ks], bk);
      }
    }

    // ---- causal mask (only when tile straddles the diagonal) ----
    if (k0 + 63 > qmin) {
      #pragma unroll
      for (int nt = 0; nt < 8; nt++) {
        int c0 = k0 + 8 * nt + 2 * tq;
        int c1 = c0 + 1;
        if (c0 > qg0) s[nt][0] = -1e30f;
        if (c1 > qg0) s[nt][1] = -1e30f;
        if (c0 > qg1) s[nt][2] = -1e30f;
        if (c1 > qg1) s[nt][3] = -1e30f;
      }
    }

    // ---- online softmax (rows r0 and r0+8) ----
    float mx0 = -1e30f, mx1 = -1e30f;
    #pragma unroll
    for (int nt = 0; nt < 8; nt++) {
      mx0 = fmaxf(mx0, fmaxf(s[nt][0], s[nt][1]));
      mx1 = fmaxf(mx1, fmaxf(s[nt][2], s[nt][3]));
    }
    mx0 = fmaxf(mx0, __shfl_xor_sync(0xffffffffu, mx0, 1));
    mx0 = fmaxf(mx0, __shfl_xor_sync(0xffffffffu, mx0, 2));
    mx1 = fmaxf(mx1, __shfl_xor_sync(0xffffffffu, mx1, 1));
    mx1 = fmaxf(mx1, __shfl_xor_sync(0xffffffffu, mx1, 2));

    float mn0 = fmaxf(m0v, mx0), mn1 = fmaxf(m1v, mx1);
    float a0 = __expf(m0v - mn0), a1 = __expf(m1v - mn1);
    m0v = mn0; m1v = mn1;

    float rs0 = 0.0f, rs1 = 0.0f;
    #pragma unroll
    for (int nt = 0; nt < 8; nt++) {
      float p0 = __expf(s[nt][0] - mn0);
      float p1 = __expf(s[nt][1] - mn0);
      float p2 = __expf(s[nt][2] - mn1);
      float p3 = __expf(s[nt][3] - mn1);
      rs0 += p0 + p1;
      rs1 += p2 + p3;
      *(uint2*)&Ps[pw + r0 * 68 + 8 * nt + 2 * tq]       = make_uint2(f2tf32(p0), f2tf32(p1));
      *(uint2*)&Ps[pw + (r0 + 8) * 68 + 8 * nt + 2 * tq] = make_uint2(f2tf32(p2), f2tf32(p3));
    }
    rs0 += __shfl_xor_sync(0xffffffffu, rs0, 1);
    rs0 += __shfl_xor_sync(0xffffffffu, rs0, 2);
    rs1 += __shfl_xor_sync(0xffffffffu, rs1, 1);
    rs1 += __shfl_xor_sync(0xffffffffu, rs1, 2);
    l0v = l0v * a0 + rs0;
    l1v = l1v * a1 + rs1;
    #pragma unroll
    for (int nt = 0; nt < 8; nt++) {
      o[nt][0] *= a0; o[nt][1] *= a0;
      o[nt][2] *= a1; o[nt][3] *= a1;
    }

    __syncwarp();   // Ps visible to whole warp

    // ---- load P a-fragments ----
    uint4 pa[8];
    #pragma unroll
    for (int ks = 0; ks < 8; ks++) {
      pa[ks].x = Ps[pw + r0 * 68 + 8 * ks + tq];
      pa[ks].y = Ps[pw + (r0 + 8) * 68 + 8 * ks + tq];
      pa[ks].z = Ps[pw + r0 * 68 + 8 * ks + tq + 4];
      pa[ks].w = Ps[pw + (r0 + 8) * 68 + 8 * ks + tq + 4];
    }

    // ---- O += P @ V ----
    #pragma unroll
    for (int nt = 0; nt < 8; nt++) {
      #pragma unroll
      for (int ks = 0; ks < 8; ks++) {
        uint2 bv;
        bv.x = Vs[(8 * ks + tq) * 72 + 8 * nt + r0];
        bv.y = Vs[(8 * ks + tq + 4) * 72 + 8 * nt + r0];
        mma_tf32(o[nt], pa[ks], bv);
      }
    }
  }

  // ---- epilogue: normalize, write [B,T,C] ----
  float inv0 = 1.0f / l0v, inv1 = 1.0f / l1v;
  float* orow0 = out + ((size_t)b * SEQ + q0 + w * 16 + r0) * EMBED + h * HDIM;
  float* orow1 = orow0 + (size_t)8 * EMBED;
  #pragma unroll
  for (int nt = 0; nt < 8; nt++) {
    *(float2*)(orow0 + 8 * nt + 2 * tq) = make_float2(o[nt][0] * inv0, o[nt][1] * inv0);
    *(float2*)(orow1 + 8 * nt + 2 * tq) = make_float2(o[nt][2] * inv1, o[nt][3] * inv1);
  }
}

// ---------------------------------------------------------------------------
extern "C" void kernel_launch(void* const* d_in, const int* in_sizes, int n_in,
                              void* d_out, int out_size)
{
  (void)in_sizes; (void)n_in; (void)out_size;
  const float* x     = (const float*)d_in[0];
  const float* qkv_w = (const float*)d_in[1];
  const float* qkv_b = (const float*)d_in[2];
  const float* out_w = (const float*)d_in[3];
  const float* out_b = (const float*)d_in[4];
  float* y = (float*)d_out;

  float *qkv = nullptr, *att = nullptr;
  cudaGetSymbolAddress((void**)&qkv, g_qkv);
  cudaGetSymbolAddress((void**)&att, g_att);

  cudaFuncSetAttribute(flash_tc,
                       cudaFuncAttributeMaxDynamicSharedMemorySize,
                       FTOT * (int)sizeof(uint32_t));

  // 1) QKV projection (TF32 tensor cores)
  gemm_tf32<<<dim3(QKVF/128, MTOT/128), 256>>>(x, qkv_w, qkv_b, qkv,
                                               MTOT, QKVF, EMBED);
  // 2) Causal flash attention (TF32 tensor cores, fp32 softmax)
  flash_tc<<<dim3(SEQ/128, BATCH*NHEAD), 256, FTOT*(int)sizeof(uint32_t)>>>(qkv, att);
  // 3) Output projection (TF32 tensor cores)
  gemm_tf32<<<dim3(EMBED/128, MTOT/128), 256>>>(att, out_w, out_b, y,
                                                MTOT, EMBED, EMBED);
}

// round 6
// speedup vs baseline: 3.0749x; 1.3383x over previous
#include <cuda_runtime.h>
#include <cstdint>

#define EMBED 1024
#define NHEAD 16
#define HDIM  64
#define BATCH 4
#define SEQ   2048
#define MTOT  (BATCH*SEQ)      /* 8192 */
#define QKVF  (3*EMBED)        /* 3072 */

// Scratch (device globals: allocation-free per harness rules)
__device__ float g_qkv[(size_t)MTOT * QKVF];   // [M, 3C]
__device__ float g_att[(size_t)MTOT * EMBED];  // [M, C]

__device__ __forceinline__ uint32_t f2tf32(float f) {
  uint32_t u;
  asm("cvt.rna.tf32.f32 %0, %1;" : "=r"(u) : "f"(f));
  return u;
}

__device__ __forceinline__ void mma_tf32(float c[4], const uint4& a, const uint2& b) {
  asm volatile(
    "mma.sync.aligned.m16n8k8.row.col.f32.tf32.tf32.f32 "
    "{%0,%1,%2,%3}, {%4,%5,%6,%7}, {%8,%9}, {%0,%1,%2,%3};\n"
    : "+f"(c[0]), "+f"(c[1]), "+f"(c[2]), "+f"(c[3])
    : "r"(a.x), "r"(a.y), "r"(a.z), "r"(a.w), "r"(b.x), "r"(b.y));
}

// ---------------------------------------------------------------------------
// TF32 tensor-core GEMM: C[M,N] = A[M,K] @ B[N,K]^T + bias[N].
// Block 128x128x32, 256 threads = 8 warps (4x2), warp tile 32x64.
// Smem: NATURAL row-major tiles, stride 36 words (==4 mod 32) so both the
// vectorized STS.128 fill and all scalar LDS.32 fragment reads are
// bank-conflict-free. Ping-pong buffers, one __syncthreads per K-chunk.
// __launch_bounds__(256,2) -> <=128 regs -> 2 blocks/SM.
// ---------------------------------------------------------------------------
#define GSTR 36
#define GTILE (128 * GSTR)            /* words per operand tile */
#define GBUF  (2 * GTILE)             /* words per ping-pong buffer (A+B) */
#define GSMEM_BYTES (2 * GBUF * 4)    /* 73728 B */

__global__ __launch_bounds__(256, 2) void gemm_tf32(
    const float* __restrict__ A, const float* __restrict__ Bm,
    const float* __restrict__ bias, float* __restrict__ C,
    int M, int N, int K)
{
  extern __shared__ uint32_t gsm[];

  const int tid  = threadIdx.x;
  const int lane = tid & 31;
  const int wid  = tid >> 5;
  const int wm   = wid & 3;          // 32-row strip
  const int wn   = wid >> 2;         // 64-col strip
  const int m0   = blockIdx.y * 128;
  const int n0   = blockIdx.x * 128;
  const int r0   = lane >> 2;        // 0..7
  const int tq   = lane & 3;         // 0..3

  const int lrow = tid >> 3;         // 0..31 (+32*i)
  const int lc4  = (tid & 7) << 2;   // 0,4,...,28

  float acc[2][8][4];
  #pragma unroll
  for (int i = 0; i < 2; i++)
    #pragma unroll
    for (int j = 0; j < 8; j++)
      #pragma unroll
      for (int r = 0; r < 4; r++) acc[i][j][r] = 0.0f;

  float4 va[4], vb[4];

  auto load_tiles = [&](int k0) {
    #pragma unroll
    for (int i = 0; i < 4; i++) {
      int r = lrow + 32 * i;
      va[i] = *(const float4*)(A  + (size_t)(m0 + r) * K + k0 + lc4);
      vb[i] = *(const float4*)(Bm + (size_t)(n0 + r) * K + k0 + lc4);
    }
  };

  auto store_tiles = [&](uint32_t* Asb, uint32_t* Bsb) {
    #pragma unroll
    for (int i = 0; i < 4; i++) {
      int r = lrow + 32 * i;
      uint4 au = make_uint4(f2tf32(va[i].x), f2tf32(va[i].y),
                            f2tf32(va[i].z), f2tf32(va[i].w));
      uint4 bu = make_uint4(f2tf32(vb[i].x), f2tf32(vb[i].y),
                            f2tf32(vb[i].z), f2tf32(vb[i].w));
      *(uint4*)&Asb[r * GSTR + lc4] = au;
      *(uint4*)&Bsb[r * GSTR + lc4] = bu;
    }
  };

  auto compute = [&](const uint32_t* Asb, const uint32_t* Bsb) {
    #pragma unroll
    for (int kt = 0; kt < 4; kt++) {
      uint4 af0, af1;
      {
        const uint32_t* p0 = Asb + (wm * 32) * GSTR + kt * 8;
        af0.x = p0[r0 * GSTR + tq];
        af0.y = p0[(r0 + 8) * GSTR + tq];
        af0.z = p0[r0 * GSTR + tq + 4];
        af0.w = p0[(r0 + 8) * GSTR + tq + 4];
        const uint32_t* p1 = p0 + 16 * GSTR;
        af1.x = p1[r0 * GSTR + tq];
        af1.y = p1[(r0 + 8) * GSTR + tq];
        af1.z = p1[r0 * GSTR + tq + 4];
        af1.w = p1[(r0 + 8) * GSTR + tq + 4];
      }
      #pragma unroll
      for (int nt = 0; nt < 8; nt++) {
        const uint32_t* pb = Bsb + (wn * 64 + nt * 8 + r0) * GSTR + kt * 8 + tq;
        uint2 bf = make_uint2(pb[0], pb[4]);
        mma_tf32(acc[0][nt], af0, bf);
        mma_tf32(acc[1][nt], af1, bf);
      }
    }
  };

  uint32_t* A0 = gsm;
  uint32_t* B0 = gsm + GTILE;
  uint32_t* A1 = gsm + GBUF;
  uint32_t* B1 = gsm + GBUF + GTILE;

  load_tiles(0);
  store_tiles(A0, B0);
  __syncthreads();

  const int nk = K >> 5;
  for (int it = 0; it < nk; it++) {
    if (it + 1 < nk) load_tiles((it + 1) << 5);

    if (it & 1) compute(A1, B1);
    else        compute(A0, B0);

    if (it + 1 < nk) {
      if ((it + 1) & 1) store_tiles(A1, B1);
      else              store_tiles(A0, B0);
      __syncthreads();
    }
  }

  // epilogue: c0:(g,2t) c1:(g,2t+1) c2:(g+8,2t) c3:(g+8,2t+1)
  const int gm_base = m0 + wm * 32 + r0;
  const int gn_base = n0 + wn * 64 + (tq << 1);
  #pragma unroll
  for (int mt2 = 0; mt2 < 2; mt2++) {
    #pragma unroll
    for (int nt = 0; nt < 8; nt++) {
      int gm = gm_base + mt2 * 16;
      int gn = gn_base + nt * 8;
      float b0 = bias[gn], b1 = bias[gn + 1];
      float2 v0 = make_float2(acc[mt2][nt][0] + b0, acc[mt2][nt][1] + b1);
      float2 v1 = make_float2(acc[mt2][nt][2] + b0, acc[mt2][nt][3] + b1);
      *(float2*)(C + (size_t)gm * N + gn)       = v0;
      *(float2*)(C + (size_t)(gm + 8) * N + gn) = v1;
    }
  }
}

// ---------------------------------------------------------------------------
// Flash attention with TF32 tensor cores (unchanged from R5).
// ---------------------------------------------------------------------------
#define FQF 0
#define FKT 8192
#define FVS (8192 + 64*68)
#define FPS (8192 + 64*68 + 64*72)
#define FTOT (8192 + 64*68 + 64*72 + 8*16*68)   /* 25856 words = 103424 B */

__global__ __launch_bounds__(256) void flash_tc(
    const float* __restrict__ qkv, float* __restrict__ out)
{
  extern __shared__ uint32_t sm[];
  uint32_t* QF = sm + FQF;
  uint32_t* Kt = sm + FKT;
  uint32_t* Vs = sm + FVS;
  uint32_t* Ps = sm + FPS;

  const int tid  = threadIdx.x;
  const int lane = tid & 31;
  const int w    = tid >> 5;
  const int bx   = blockIdx.x;
  const int bh   = blockIdx.y;
  const int b    = bh >> 4;
  const int h    = bh & 15;
  const int q0   = bx * 128;

  const float* qbase = qkv + ((size_t)b * SEQ + q0) * QKVF + h * HDIM;
  const float* kbase = qkv + ((size_t)b * SEQ) * QKVF + EMBED + h * HDIM;
  const float* vbase = kbase + EMBED;

  for (int e = tid; e < 128 * 16; e += 256) {
    int r = e >> 4, d4 = (e & 15) << 2;
    float4 qv = *(const float4*)(qbase + (size_t)r * QKVF + d4);
    float qf[4] = {qv.x, qv.y, qv.z, qv.w};
    int wq = r >> 4, rr = r & 15;
    #pragma unroll
    for (int j = 0; j < 4; j++) {
      int d = d4 + j, ks = d >> 3, dd = d & 7;
      int ln = ((rr & 7) << 2) | (dd & 3);
      int rg = (rr >> 3) | ((dd >> 2) << 1);
      QF[((((wq << 3) | ks) << 5 | ln) << 2) | rg] = f2tf32(qf[j] * 0.125f);
    }
  }

  const int r0 = lane >> 2;
  const int tq = lane & 3;
  const int qg0 = q0 + w * 16 + r0;
  const int qg1 = qg0 + 8;
  const int qmin = q0 + w * 16;
  const int qmax = qmin + 15;
  const int pw = w * (16 * 68);

  float m0v = -1e30f, m1v = -1e30f, l0v = 0.0f, l1v = 0.0f;
  float o[8][4];
  #pragma unroll
  for (int nt = 0; nt < 8; nt++)
    #pragma unroll
    for (int j = 0; j < 4; j++) o[nt][j] = 0.0f;

  const int nkv = 2 * bx + 2;
  for (int kv = 0; kv < nkv; kv++) {
    const int k0 = kv * 64;
    __syncthreads();
    for (int e = tid; e < 64 * 16; e += 256) {
      int r = e >> 4, d4 = (e & 15) << 2;
      float4 kf4 = *(const float4*)(kbase + (size_t)(k0 + r) * QKVF + d4);
      float4 vf4 = *(const float4*)(vbase + (size_t)(k0 + r) * QKVF + d4);
      uint4 ku = make_uint4(f2tf32(kf4.x), f2tf32(kf4.y), f2tf32(kf4.z), f2tf32(kf4.w));
      uint4 vu = make_uint4(f2tf32(vf4.x), f2tf32(vf4.y), f2tf32(vf4.z), f2tf32(vf4.w));
      *(uint4*)&Kt[r * 68 + d4] = ku;
      *(uint4*)&Vs[r * 72 + d4] = vu;
    }
    __syncthreads();

    if (k0 > qmax) continue;

    uint4 qa[8];
    #pragma unroll
    for (int ks = 0; ks < 8; ks++)
      qa[ks] = *(const uint4*)&QF[(((w << 3) | ks) << 5 | lane) << 2];

    float s[8][4];
    #pragma unroll
    for (int nt = 0; nt < 8; nt++) {
      s[nt][0] = s[nt][1] = s[nt][2] = s[nt][3] = 0.0f;
      #pragma unroll
      for (int ks = 0; ks < 8; ks++) {
        uint2 bk;
        bk.x = Kt[(8 * nt + r0) * 68 + 8 * ks + tq];
        bk.y = Kt[(8 * nt + r0) * 68 + 8 * ks + tq + 4];
        mma_tf32(s[nt], qa[ks], bk);
      }
    }

    if (k0 + 63 > qmin) {
      #pragma unroll
      for (int nt = 0; nt < 8; nt++) {
        int c0 = k0 + 8 * nt + 2 * tq;
        int c1 = c0 + 1;
        if (c0 > qg0) s[nt][0] = -1e30f;
        if (c1 > qg0) s[nt][1] = -1e30f;
        if (c0 > qg1) s[nt][2] = -1e30f;
        if (c1 > qg1) s[nt][3] = -1e30f;
      }
    }

    float mx0 = -1e30f, mx1 = -1e30f;
    #pragma unroll
    for (int nt = 0; nt < 8; nt++) {
      mx0 = fmaxf(mx0, fmaxf(s[nt][0], s[nt][1]));
      mx1 = fmaxf(mx1, fmaxf(s[nt][2], s[nt][3]));
    }
    mx0 = fmaxf(mx0, __shfl_xor_sync(0xffffffffu, mx0, 1));
    mx0 = fmaxf(mx0, __shfl_xor_sync(0xffffffffu, mx0, 2));
    mx1 = fmaxf(mx1, __shfl_xor_sync(0xffffffffu, mx1, 1));
    mx1 = fmaxf(mx1, __shfl_xor_sync(0xffffffffu, mx1, 2));

    float mn0 = fmaxf(m0v, mx0), mn1 = fmaxf(m1v, mx1);
    float a0 = __expf(m0v - mn0), a1 = __expf(m1v - mn1);
    m0v = mn0; m1v = mn1;

    float rs0 = 0.0f, rs1 = 0.0f;
    #pragma unroll
    for (int nt = 0; nt < 8; nt++) {
      float p0 = __expf(s[nt][0] - mn0);
      float p1 = __expf(s[nt][1] - mn0);
      float p2 = __expf(s[nt][2] - mn1);
      float p3 = __expf(s[nt][3] - mn1);
      rs0 += p0 + p1;
      rs1 += p2 + p3;
      *(uint2*)&Ps[pw + r0 * 68 + 8 * nt + 2 * tq]       = make_uint2(f2tf32(p0), f2tf32(p1));
      *(uint2*)&Ps[pw + (r0 + 8) * 68 + 8 * nt + 2 * tq] = make_uint2(f2tf32(p2), f2tf32(p3));
    }
    rs0 += __shfl_xor_sync(0xffffffffu, rs0, 1);
    rs0 += __shfl_xor_sync(0xffffffffu, rs0, 2);
    rs1 += __shfl_xor_sync(0xffffffffu, rs1, 1);
    rs1 += __shfl_xor_sync(0xffffffffu, rs1, 2);
    l0v = l0v * a0 + rs0;
    l1v = l1v * a1 + rs1;
    #pragma unroll
    for (int nt = 0; nt < 8; nt++) {
      o[nt][0] *= a0; o[nt][1] *= a0;
      o[nt][2] *= a1; o[nt][3] *= a1;
    }

    __syncwarp();

    uint4 pa[8];
    #pragma unroll
    for (int ks = 0; ks < 8; ks++) {
      pa[ks].x = Ps[pw + r0 * 68 + 8 * ks + tq];
      pa[ks].y = Ps[pw + (r0 + 8) * 68 + 8 * ks + tq];
      pa[ks].z = Ps[pw + r0 * 68 + 8 * ks + tq + 4];
      pa[ks].w = Ps[pw + (r0 + 8) * 68 + 8 * ks + tq + 4];
    }

    #pragma unroll
    for (int nt = 0; nt < 8; nt++) {
      #pragma unroll
      for (int ks = 0; ks < 8; ks++) {
        uint2 bv;
        bv.x = Vs[(8 * ks + tq) * 72 + 8 * nt + r0];
        bv.y = Vs[(8 * ks + tq + 4) * 72 + 8 * nt + r0];
        mma_tf32(o[nt], pa[ks], bv);
      }
    }
  }

  float inv0 = 1.0f / l0v, inv1 = 1.0f / l1v;
  float* orow0 = out + ((size_t)b * SEQ + q0 + w * 16 + r0) * EMBED + h * HDIM;
  float* orow1 = orow0 + (size_t)8 * EMBED;
  #pragma unroll
  for (int nt = 0; nt < 8; nt++) {
    *(float2*)(orow0 + 8 * nt + 2 * tq) = make_float2(o[nt][0] * inv0, o[nt][1] * inv0);
    *(float2*)(orow1 + 8 * nt + 2 * tq) = make_float2(o[nt][2] * inv1, o[nt][3] * inv1);
  }
}

// ---------------------------------------------------------------------------
extern "C" void kernel_launch(void* const* d_in, const int* in_sizes, int n_in,
                              void* d_out, int out_size)
{
  (void)in_sizes; (void)n_in; (void)out_size;
  const float* x     = (const float*)d_in[0];
  const float* qkv_w = (const float*)d_in[1];
  const float* qkv_b = (const float*)d_in[2];
  const float* out_w = (const float*)d_in[3];
  const float* out_b = (const float*)d_in[4];
  float* y = (float*)d_out;

  float *qkv = nullptr, *att = nullptr;
  cudaGetSymbolAddress((void**)&qkv, g_qkv);
  cudaGetSymbolAddress((void**)&att, g_att);

  cudaFuncSetAttribute(gemm_tf32,
                       cudaFuncAttributeMaxDynamicSharedMemorySize, GSMEM_BYTES);
  cudaFuncSetAttribute(flash_tc,
                       cudaFuncAttributeMaxDynamicSharedMemorySize,
                       FTOT * (int)sizeof(uint32_t));

  // 1) QKV projection (TF32 tensor cores)
  gemm_tf32<<<dim3(QKVF/128, MTOT/128), 256, GSMEM_BYTES>>>(
      x, qkv_w, qkv_b, qkv, MTOT, QKVF, EMBED);
  // 2) Causal flash attention (TF32 tensor cores, fp32 softmax)
  flash_tc<<<dim3(SEQ/128, BATCH*NHEAD), 256, FTOT*(int)sizeof(uint32_t)>>>(qkv, att);
  // 3) Output projection (TF32 tensor cores)
  gemm_tf32<<<dim3(EMBED/128, MTOT/128), 256, GSMEM_BYTES>>>(
      att, out_w, out_b, y, MTOT, EMBED, EMBED);
}

// round 8
// speedup vs baseline: 3.0905x; 1.0051x over previous
#include <cuda_runtime.h>
#include <cstdint>

#define EMBED 1024
#define NHEAD 16
#define HDIM  64
#define BATCH 4
#define SEQ   2048
#define MTOT  (BATCH*SEQ)      /* 8192 */
#define QKVF  (3*EMBED)        /* 3072 */

// Scratch (device globals: allocation-free per harness rules)
__device__ float g_qkv[(size_t)MTOT * QKVF];   // [M, 3C]
__device__ float g_att[(size_t)MTOT * EMBED];  // [M, C]

__device__ __forceinline__ uint32_t f2tf32(float f) {
  uint32_t u;
  asm("cvt.rna.tf32.f32 %0, %1;" : "=r"(u) : "f"(f));
  return u;
}

__device__ __forceinline__ void mma_tf32(float c[4], const uint4& a, const uint2& b) {
  asm volatile(
    "mma.sync.aligned.m16n8k8.row.col.f32.tf32.tf32.f32 "
    "{%0,%1,%2,%3}, {%4,%5,%6,%7}, {%8,%9}, {%0,%1,%2,%3};\n"
    : "+f"(c[0]), "+f"(c[1]), "+f"(c[2]), "+f"(c[3])
    : "r"(a.x), "r"(a.y), "r"(a.z), "r"(a.w), "r"(b.x), "r"(b.y));
}

__device__ __forceinline__ uint32_t smem_u32(const void* p) {
  uint32_t a;
  asm("{ .reg .u64 t; cvta.to.shared.u64 t, %1; cvt.u32.u64 %0, t; }"
      : "=r"(a) : "l"(p));
  return a;
}

__device__ __forceinline__ void cp16(uint32_t dst, const void* src) {
  asm volatile("cp.async.ca.shared.global [%0], [%1], 16;"
               :: "r"(dst), "l"(src) : "memory");
}

// ===========================================================================
// TF32 GEMM via mma.sync: C[M,N] = A[M,K] @ B[N,K]^T + bias[N]
// CTA 128x128x32, 128 threads = 4 warps of 64x64 (minimal cross-warp operand
// re-reads: A shared 2x, B shared 2x -> 512 read-wavefronts per chunk).
// Fills: cp.async (raw fp32, 3-stage ring); cvt.rna.tf32 on the read side.
// Smem stride 36 words -> all fragment LDS.32 reads bank-conflict-free.
// ===========================================================================
#define GSTRW 36
#define GTILEW (128 * GSTRW)         /* 4608 words per operand tile */
#define GSTAGEW (2 * GTILEW)         /* 9216 words per stage (A+B) */
#define GSTAGES 3
#define GSMEM_BYTES (GSTAGES * GSTAGEW * 4)   /* 110592 B */

__global__ __launch_bounds__(128, 2) void gemm_cpa(
    const float* __restrict__ A, const float* __restrict__ Bm,
    const float* __restrict__ bias, float* __restrict__ C,
    int M, int N, int K)
{
  extern __shared__ float gsm[];
  const uint32_t sb = smem_u32(gsm);

  const int tid  = threadIdx.x;
  const int lane = tid & 31;
  const int wid  = tid >> 5;
  const int wm   = wid & 1;          // 64-row strip
  const int wn   = wid >> 1;         // 64-col strip
  const int m0   = blockIdx.y * 128;
  const int n0   = blockIdx.x * 128;
  const int r0   = lane >> 2;        // 0..7
  const int tq   = lane & 3;         // 0..3

  float acc[4][8][4];
  #pragma unroll
  for (int i = 0; i < 4; i++)
    #pragma unroll
    for (int j = 0; j < 8; j++)
      #pragma unroll
      for (int r = 0; r < 4; r++) acc[i][j][r] = 0.0f;

  // ---- async fill of one stage (A tile 128x32 + B tile 128x32, fp32) ----
  auto fill = [&](int s, int k0) {
    const uint32_t base = sb + (uint32_t)s * GSTAGEW * 4;
    #pragma unroll
    for (int i = 0; i < 8; i++) {
      int idx = tid + 128 * i;           // 0..1023
      int row = idx >> 3, g = idx & 7;
      uint32_t off = (uint32_t)(row * GSTRW + g * 4) * 4;
      cp16(base + off,              A  + (size_t)(m0 + row) * K + k0 + g * 4);
      cp16(base + GTILEW * 4 + off, Bm + (size_t)(n0 + row) * K + k0 + g * 4);
    }
    asm volatile("cp.async.commit_group;" ::: "memory");
  };

  auto compute = [&](int s) {
    const float* As = gsm + (size_t)s * GSTAGEW;
    const float* Bs = As + GTILEW;
    #pragma unroll
    for (int kt = 0; kt < 4; kt++) {
      uint4 af[4];
      #pragma unroll
      for (int mf = 0; mf < 4; mf++) {
        const float* pa = As + (wm * 64 + mf * 16) * GSTRW + kt * 8;
        af[mf].x = f2tf32(pa[r0 * GSTRW + tq]);
        af[mf].y = f2tf32(pa[(r0 + 8) * GSTRW + tq]);
        af[mf].z = f2tf32(pa[r0 * GSTRW + tq + 4]);
        af[mf].w = f2tf32(pa[(r0 + 8) * GSTRW + tq + 4]);
      }
      #pragma unroll
      for (int nt = 0; nt < 8; nt++) {
        const float* pb = Bs + (wn * 64 + nt * 8 + r0) * GSTRW + kt * 8 + tq;
        uint2 bf = make_uint2(f2tf32(pb[0]), f2tf32(pb[4]));
        #pragma unroll
        for (int mf = 0; mf < 4; mf++)
          mma_tf32(acc[mf][nt], af[mf], bf);
      }
    }
  };

  const int nk = K >> 5;               // K/32 (>=2 always here)
  fill(0, 0);
  fill(1, 32);

  for (int t = 0; t < nk; t++) {
    asm volatile("cp.async.wait_group 1;" ::: "memory");
    __syncthreads();
    if (t + 2 < nk) fill((t + 2) % GSTAGES, (t + 2) << 5);
    compute(t % GSTAGES);
  }

  // ---- epilogue ----
  const int gn_base = n0 + wn * 64 + (tq << 1);
  #pragma unroll
  for (int mf = 0; mf < 4; mf++) {
    int gm = m0 + wm * 64 + mf * 16 + r0;
    #pragma unroll
    for (int nt = 0; nt < 8; nt++) {
      int gn = gn_base + nt * 8;
      float b0 = bias[gn], b1 = bias[gn + 1];
      float2 v0 = make_float2(acc[mf][nt][0] + b0, acc[mf][nt][1] + b1);
      float2 v1 = make_float2(acc[mf][nt][2] + b0, acc[mf][nt][3] + b1);
      *(float2*)(C + (size_t)gm * N + gn)       = v0;
      *(float2*)(C + (size_t)(gm + 8) * N + gn) = v1;
    }
  }
}

// ===========================================================================
// Flash attention, TF32 mma.sync, 128 threads = 4 warps of 32q x 64k tiles.
// Each K/V b-fragment serves TWO m-fragments (halves cross-warp K/V re-reads
// vs the 16q warp tile). Same verified fragment mappings as R5/R6.
// Smem: QF fragment-layout Q [w][m][ks][lane][4]; Kt [k][d] stride 68;
//       Vs [k][d] stride 72; Ps [qrow(128)][68].
// ===========================================================================
#define FQF 0
#define FKT 8192
#define FVS (8192 + 64*68)
#define FPS (8192 + 64*68 + 64*72)
#define FTOT (8192 + 64*68 + 64*72 + 128*68)   /* 25856 words = 103424 B */

__global__ __launch_bounds__(128) void flash_tc(
    const float* __restrict__ qkv, float* __restrict__ out)
{
  extern __shared__ uint32_t sm[];
  uint32_t* QF = sm + FQF;
  uint32_t* Kt = sm + FKT;
  uint32_t* Vs = sm + FVS;
  uint32_t* Ps = sm + FPS;

  const int tid  = threadIdx.x;
  const int lane = tid & 31;
  const int w    = tid >> 5;
  const int bx   = blockIdx.x;
  const int bh   = blockIdx.y;
  const int b    = bh >> 4;
  const int h    = bh & 15;
  const int q0   = bx * 128;

  const float* qbase = qkv + ((size_t)b * SEQ + q0) * QKVF + h * HDIM;
  const float* kbase = qkv + ((size_t)b * SEQ) * QKVF + EMBED + h * HDIM;
  const float* vbase = kbase + EMBED;

  // ---- Q scatter into fragment layout (once per block), scaled by 1/8 ----
  for (int e = tid; e < 128 * 16; e += 128) {
    int r = e >> 4, d4 = (e & 15) << 2;
    float4 qv = *(const float4*)(qbase + (size_t)r * QKVF + d4);
    float qf[4] = {qv.x, qv.y, qv.z, qv.w};
    int wq = r >> 5, m = (r >> 4) & 1, rr = r & 15;
    #pragma unroll
    for (int j = 0; j < 4; j++) {
      int d = d4 + j, ks = d >> 3, dd = d & 7;
      int ln = ((rr & 7) << 2) | (dd & 3);
      int rg = (rr >> 3) | ((dd >> 2) << 1);
      QF[(((((wq << 1) | m) << 3 | ks) << 5 | ln) << 2) | rg] = f2tf32(qf[j] * 0.125f);
    }
  }

  const int r0 = lane >> 2;
  const int tq = lane & 3;
  const int qmin = q0 + w * 32;
  const int qmax = qmin + 31;
  const int qg[2] = { qmin + r0, qmin + 16 + r0 };   // +8 for upper half

  float mrow[2][2], lrow[2][2];
  #pragma unroll
  for (int m = 0; m < 2; m++) {
    mrow[m][0] = mrow[m][1] = -1e30f;
    lrow[m][0] = lrow[m][1] = 0.0f;
  }
  float o[2][8][4];
  #pragma unroll
  for (int m = 0; m < 2; m++)
    #pragma unroll
    for (int nt = 0; nt < 8; nt++)
      #pragma unroll
      for (int j = 0; j < 4; j++) o[m][nt][j] = 0.0f;

  const int nkv = 2 * bx + 2;
  for (int kv = 0; kv < nkv; kv++) {
    const int k0 = kv * 64;
    __syncthreads();   // previous tile fully consumed; QF ready on kv==0
    for (int e = tid; e < 64 * 16; e += 128) {
      int r = e >> 4, d4 = (e & 15) << 2;
      float4 kf4 = *(const float4*)(kbase + (size_t)(k0 + r) * QKVF + d4);
      float4 vf4 = *(const float4*)(vbase + (size_t)(k0 + r) * QKVF + d4);
      uint4 ku = make_uint4(f2tf32(kf4.x), f2tf32(kf4.y), f2tf32(kf4.z), f2tf32(kf4.w));
      uint4 vu = make_uint4(f2tf32(vf4.x), f2tf32(vf4.y), f2tf32(vf4.z), f2tf32(vf4.w));
      *(uint4*)&Kt[r * 68 + d4] = ku;
      *(uint4*)&Vs[r * 72 + d4] = vu;
    }
    __syncthreads();

    if (k0 > qmax) continue;   // whole key tile above this warp's rows

    // ---- S = Q @ K^T : K b-frags shared across both m-frags ----
    float s[2][8][4];
    #pragma unroll
    for (int m = 0; m < 2; m++)
      #pragma unroll
      for (int nt = 0; nt < 8; nt++)
        s[m][nt][0] = s[m][nt][1] = s[m][nt][2] = s[m][nt][3] = 0.0f;

    #pragma unroll
    for (int ks = 0; ks < 8; ks++) {
      uint4 qa0 = *(const uint4*)&QF[((((w << 1) << 3 | ks) << 5 | lane) << 2)];
      uint4 qa1 = *(const uint4*)&QF[(((((w << 1) | 1) << 3 | ks) << 5 | lane) << 2)];
      #pragma unroll
      for (int nt = 0; nt < 8; nt++) {
        uint2 bk;
        bk.x = Kt[(8 * nt + r0) * 68 + 8 * ks + tq];
        bk.y = Kt[(8 * nt + r0) * 68 + 8 * ks + tq + 4];
        mma_tf32(s[0][nt], qa0, bk);
        mma_tf32(s[1][nt], qa1, bk);
      }
    }

    // ---- causal mask ----
    if (k0 + 63 > qmin) {
      #pragma unroll
      for (int m = 0; m < 2; m++) {
        #pragma unroll
        for (int nt = 0; nt < 8; nt++) {
          int c0 = k0 + 8 * nt + 2 * tq;
          int c1 = c0 + 1;
          if (c0 > qg[m])     s[m][nt][0] = -1e30f;
          if (c1 > qg[m])     s[m][nt][1] = -1e30f;
          if (c0 > qg[m] + 8) s[m][nt][2] = -1e30f;
          if (c1 > qg[m] + 8) s[m][nt][3] = -1e30f;
        }
      }
    }

    // ---- online softmax per m-frag (rows r0 and r0+8) ----
    #pragma unroll
    for (int m = 0; m < 2; m++) {
      float mx0 = -1e30f, mx1 = -1e30f;
      #pragma unroll
      for (int nt = 0; nt < 8; nt++) {
        mx0 = fmaxf(mx0, fmaxf(s[m][nt][0], s[m][nt][1]));
        mx1 = fmaxf(mx1, fmaxf(s[m][nt][2], s[m][nt][3]));
      }
      mx0 = fmaxf(mx0, __shfl_xor_sync(0xffffffffu, mx0, 1));
      mx0 = fmaxf(mx0, __shfl_xor_sync(0xffffffffu, mx0, 2));
      mx1 = fmaxf(mx1, __shfl_xor_sync(0xffffffffu, mx1, 1));
      mx1 = fmaxf(mx1, __shfl_xor_sync(0xffffffffu, mx1, 2));

      float mn0 = fmaxf(mrow[m][0], mx0), mn1 = fmaxf(mrow[m][1], mx1);
      float a0 = __expf(mrow[m][0] - mn0), a1 = __expf(mrow[m][1] - mn1);
      mrow[m][0] = mn0; mrow[m][1] = mn1;

      const int prow = w * 32 + m * 16 + r0;
      float rs0 = 0.0f, rs1 = 0.0f;
      #pragma unroll
      for (int nt = 0; nt < 8; nt++) {
        float p0 = __expf(s[m][nt][0] - mn0);
        float p1 = __expf(s[m][nt][1] - mn0);
        float p2 = __expf(s[m][nt][2] - mn1);
        float p3 = __expf(s[m][nt][3] - mn1);
        rs0 += p0 + p1;
        rs1 += p2 + p3;
        *(uint2*)&Ps[prow * 68 + 8 * nt + 2 * tq]       = make_uint2(f2tf32(p0), f2tf32(p1));
        *(uint2*)&Ps[(prow + 8) * 68 + 8 * nt + 2 * tq] = make_uint2(f2tf32(p2), f2tf32(p3));
      }
      rs0 += __shfl_xor_sync(0xffffffffu, rs0, 1);
      rs0 += __shfl_xor_sync(0xffffffffu, rs0, 2);
      rs1 += __shfl_xor_sync(0xffffffffu, rs1, 1);
      rs1 += __shfl_xor_sync(0xffffffffu, rs1, 2);
      lrow[m][0] = lrow[m][0] * a0 + rs0;
      lrow[m][1] = lrow[m][1] * a1 + rs1;
      #pragma unroll
      for (int nt = 0; nt < 8; nt++) {
        o[m][nt][0] *= a0; o[m][nt][1] *= a0;
        o[m][nt][2] *= a1; o[m][nt][3] *= a1;
      }
    }

    __syncwarp();   // Ps (per-warp rows) visible within warp

    // ---- O += P @ V : V b-frags shared across both m-frags ----
    #pragma unroll
    for (int ks = 0; ks < 8; ks++) {
      uint4 pa0, pa1;
      {
        const int prow = w * 32 + r0;
        pa0.x = Ps[prow * 68 + 8 * ks + tq];
        pa0.y = Ps[(prow + 8) * 68 + 8 * ks + tq];
        pa0.z = Ps[prow * 68 + 8 * ks + tq + 4];
        pa0.w = Ps[(prow + 8) * 68 + 8 * ks + tq + 4];
        pa1.x = Ps[(prow + 16) * 68 + 8 * ks + tq];
        pa1.y = Ps[(prow + 24) * 68 + 8 * ks + tq];
        pa1.z = Ps[(prow + 16) * 68 + 8 * ks + tq + 4];
        pa1.w = Ps[(prow + 24) * 68 + 8 * ks + tq + 4];
      }
      #pragma unroll
      for (int nt = 0; nt < 8; nt++) {
        uint2 bv;
        bv.x = Vs[(8 * ks + tq) * 72 + 8 * nt + r0];
        bv.y = Vs[(8 * ks + tq + 4) * 72 + 8 * nt + r0];
        mma_tf32(o[0][nt], pa0, bv);
        mma_tf32(o[1][nt], pa1, bv);
      }
    }
  }

  // ---- epilogue: normalize, write [B,T,C] ----
  #pragma unroll
  for (int m = 0; m < 2; m++) {
    float inv0 = 1.0f / lrow[m][0], inv1 = 1.0f / lrow[m][1];
    float* orow0 = out + ((size_t)b * SEQ + q0 + w * 32 + m * 16 + r0) * EMBED + h * HDIM;
    float* orow1 = orow0 + (size_t)8 * EMBED;
    #pragma unroll
    for (int nt = 0; nt < 8; nt++) {
      *(float2*)(orow0 + 8 * nt + 2 * tq) =
          make_float2(o[m][nt][0] * inv0, o[m][nt][1] * inv0);
      *(float2*)(orow1 + 8 * nt + 2 * tq) =
          make_float2(o[m][nt][2] * inv1, o[m][nt][3] * inv1);
    }
  }
}

// ---------------------------------------------------------------------------
extern "C" void kernel_launch(void* const* d_in, const int* in_sizes, int n_in,
                              void* d_out, int out_size)
{
  (void)in_sizes; (void)n_in; (void)out_size;
  const float* x     = (const float*)d_in[0];
  const float* qkv_w = (const float*)d_in[1];
  const float* qkv_b = (const float*)d_in[2];
  const float* out_w = (const float*)d_in[3];
  const float* out_b = (const float*)d_in[4];
  float* y = (float*)d_out;

  float *qkv = nullptr, *att = nullptr;
  cudaGetSymbolAddress((void**)&qkv, g_qkv);
  cudaGetSymbolAddress((void**)&att, g_att);

  cudaFuncSetAttribute(gemm_cpa,
                       cudaFuncAttributeMaxDynamicSharedMemorySize, GSMEM_BYTES);
  cudaFuncSetAttribute(flash_tc,
                       cudaFuncAttributeMaxDynamicSharedMemorySize,
                       FTOT * (int)sizeof(uint32_t));

  // 1) QKV projection
  gemm_cpa<<<dim3(QKVF/128, MTOT/128), 128, GSMEM_BYTES>>>(
      x, qkv_w, qkv_b, qkv, MTOT, QKVF, EMBED);
  // 2) Causal flash attention
  flash_tc<<<dim3(SEQ/128, BATCH*NHEAD), 128, FTOT*(int)sizeof(uint32_t)>>>(qkv, att);
  // 3) Output projection
  gemm_cpa<<<dim3(EMBED/128, MTOT/128), 128, GSMEM_BYTES>>>(
      att, out_w, out_b, y, MTOT, EMBED, EMBED);
}